// round 2
// baseline (speedup 1.0000x reference)
#include <cuda_runtime.h>
#include <cstdint>

#define N_NODES 100000
#define N_EDGES 6400000
#define F_IN    128
#define HID     16

// ---------------- scratch (static device globals; no runtime alloc) ----------
__device__ __align__(16) int   g_src[N_EDGES];
__device__ __align__(16) int   g_dst[N_EDGES];
__device__ __align__(16) float g_norm[N_EDGES];
__device__ float g_deg[N_NODES];
__device__ float g_dis[N_NODES];
__device__ __align__(64) float g_y  [N_NODES * HID];   // per-layer messages
__device__ __align__(64) float g_agg[N_NODES * HID];   // per-layer aggregate
__device__ float g_y4  [N_NODES];
__device__ float g_agg4[N_NODES];
__device__ int   g_is64;

// ---------------- kernels ----------------------------------------------------

// Detect whether the edge tensor is int64 or int32 (JAX x64-disabled downcast).
__global__ void k_detect(const long long* __restrict__ e64) {
    int is64 = 1;
#pragma unroll
    for (int i = 0; i < 16; i++) {
        long long v = e64[i];
        if (v < 0 || v >= N_NODES) { is64 = 0; break; }
    }
    g_is64 = is64;
}

__global__ void k_init_deg() {
    int i = blockIdx.x * blockDim.x + threadIdx.x;
    if (i < N_NODES) g_deg[i] = 1.0f;   // self-loop weight
}

// edge indices (either dtype) -> int32 scratch + weighted in-degree
__global__ void k_edge_pre(const void* __restrict__ edges,
                           const float* __restrict__ w) {
    int e = blockIdx.x * blockDim.x + threadIdx.x;
    if (e >= N_EDGES) return;
    int s, d;
    if (g_is64) {
        const long long* p = (const long long*)edges;
        s = (int)p[e];
        d = (int)p[N_EDGES + e];
    } else {
        const int* p = (const int*)edges;
        s = p[e];
        d = p[N_EDGES + e];
    }
    // defensive clamp: converts any surprise into a rel_err signal, not a crash
    s = min(max(s, 0), N_NODES - 1);
    d = min(max(d, 0), N_NODES - 1);
    g_src[e] = s;
    g_dst[e] = d;
    atomicAdd(&g_deg[d], w[e]);
}

__global__ void k_dis() {
    int i = blockIdx.x * blockDim.x + threadIdx.x;
    if (i < N_NODES) g_dis[i] = rsqrtf(g_deg[i]);   // deg >= 1 always
}

__global__ void k_norm(const float* __restrict__ w) {
    int e = blockIdx.x * blockDim.x + threadIdx.x;
    if (e >= N_EDGES) return;
    g_norm[e] = g_dis[g_src[e]] * w[e] * g_dis[g_dst[e]];
}

// Layer 1 dense transform: y = x @ W1 ; agg = y * dis^2 (self-loop term)
__global__ void k_t1(const float* __restrict__ x, const float* __restrict__ W1) {
    __shared__ float Ws[F_IN * HID];
    for (int t = threadIdx.x; t < F_IN * HID; t += blockDim.x) Ws[t] = W1[t];
    __syncthreads();

    int i = blockIdx.x * blockDim.x + threadIdx.x;
    if (i >= N_NODES) return;

    float acc[HID];
#pragma unroll
    for (int c = 0; c < HID; c++) acc[c] = 0.f;

    const float4* xr = reinterpret_cast<const float4*>(x + (size_t)i * F_IN);
#pragma unroll 8
    for (int k4 = 0; k4 < F_IN / 4; k4++) {
        float4 xv = __ldg(&xr[k4]);
        float xk[4] = {xv.x, xv.y, xv.z, xv.w};
#pragma unroll
        for (int j = 0; j < 4; j++) {
            const float4* wrow = reinterpret_cast<const float4*>(&Ws[(k4 * 4 + j) * HID]);
#pragma unroll
            for (int c4 = 0; c4 < 4; c4++) {
                float4 wv = wrow[c4];
                acc[c4 * 4 + 0] = fmaf(xk[j], wv.x, acc[c4 * 4 + 0]);
                acc[c4 * 4 + 1] = fmaf(xk[j], wv.y, acc[c4 * 4 + 1]);
                acc[c4 * 4 + 2] = fmaf(xk[j], wv.z, acc[c4 * 4 + 2]);
                acc[c4 * 4 + 3] = fmaf(xk[j], wv.w, acc[c4 * 4 + 3]);
            }
        }
    }

    float dis = g_dis[i];
    float d2 = dis * dis;
    float4* yo = reinterpret_cast<float4*>(g_y   + (size_t)i * HID);
    float4* ao = reinterpret_cast<float4*>(g_agg + (size_t)i * HID);
#pragma unroll
    for (int q = 0; q < 4; q++) {
        float4 v = make_float4(acc[q*4+0], acc[q*4+1], acc[q*4+2], acc[q*4+3]);
        yo[q] = v;
        ao[q] = make_float4(v.x * d2, v.y * d2, v.z * d2, v.w * d2);
    }
}

// Layers 2/3: a = relu(agg + b_prev); y = a @ W ; agg = y * dis^2
__global__ void k_tmid(const float* __restrict__ W, const float* __restrict__ bprev) {
    __shared__ float Ws[HID * HID];
    __shared__ float bs[HID];
    for (int t = threadIdx.x; t < HID * HID; t += blockDim.x) Ws[t] = W[t];
    if (threadIdx.x < HID) bs[threadIdx.x] = bprev[threadIdx.x];
    __syncthreads();

    int i = blockIdx.x * blockDim.x + threadIdx.x;
    if (i >= N_NODES) return;

    float a[HID];
    const float4* ar = reinterpret_cast<const float4*>(g_agg + (size_t)i * HID);
#pragma unroll
    for (int q = 0; q < 4; q++) {
        float4 v = ar[q];
        a[q*4+0] = fmaxf(v.x + bs[q*4+0], 0.f);
        a[q*4+1] = fmaxf(v.y + bs[q*4+1], 0.f);
        a[q*4+2] = fmaxf(v.z + bs[q*4+2], 0.f);
        a[q*4+3] = fmaxf(v.w + bs[q*4+3], 0.f);
    }

    float acc[HID];
#pragma unroll
    for (int c = 0; c < HID; c++) acc[c] = 0.f;
#pragma unroll
    for (int k = 0; k < HID; k++) {
        const float4* wrow = reinterpret_cast<const float4*>(&Ws[k * HID]);
#pragma unroll
        for (int c4 = 0; c4 < 4; c4++) {
            float4 wv = wrow[c4];
            acc[c4*4+0] = fmaf(a[k], wv.x, acc[c4*4+0]);
            acc[c4*4+1] = fmaf(a[k], wv.y, acc[c4*4+1]);
            acc[c4*4+2] = fmaf(a[k], wv.z, acc[c4*4+2]);
            acc[c4*4+3] = fmaf(a[k], wv.w, acc[c4*4+3]);
        }
    }

    float dis = g_dis[i];
    float d2 = dis * dis;
    float4* yo = reinterpret_cast<float4*>(g_y   + (size_t)i * HID);
    float4* ao = reinterpret_cast<float4*>(g_agg + (size_t)i * HID);
#pragma unroll
    for (int q = 0; q < 4; q++) {
        float4 v = make_float4(acc[q*4+0], acc[q*4+1], acc[q*4+2], acc[q*4+3]);
        yo[q] = v;
        ao[q] = make_float4(v.x * d2, v.y * d2, v.z * d2, v.w * d2);
    }
}

// Layer 4: a = relu(agg + b3); y = a @ W4 (scalar); agg4 = y * dis^2
__global__ void k_t4(const float* __restrict__ W4, const float* __restrict__ b3) {
    __shared__ float W4s[HID];
    __shared__ float bs[HID];
    if (threadIdx.x < HID) { W4s[threadIdx.x] = W4[threadIdx.x]; bs[threadIdx.x] = b3[threadIdx.x]; }
    __syncthreads();

    int i = blockIdx.x * blockDim.x + threadIdx.x;
    if (i >= N_NODES) return;

    const float4* ar = reinterpret_cast<const float4*>(g_agg + (size_t)i * HID);
    float y = 0.f;
#pragma unroll
    for (int q = 0; q < 4; q++) {
        float4 v = ar[q];
        y = fmaf(fmaxf(v.x + bs[q*4+0], 0.f), W4s[q*4+0], y);
        y = fmaf(fmaxf(v.y + bs[q*4+1], 0.f), W4s[q*4+1], y);
        y = fmaf(fmaxf(v.z + bs[q*4+2], 0.f), W4s[q*4+2], y);
        y = fmaf(fmaxf(v.w + bs[q*4+3], 0.f), W4s[q*4+3], y);
    }
    float dis = g_dis[i];
    g_y4[i] = y;
    g_agg4[i] = y * dis * dis;
}

// 16-wide edge scatter: agg[dst] += y[src] * norm   (float4 vector atomics)
__global__ void k_edge_agg16() {
    int e = blockIdx.x * blockDim.x + threadIdx.x;
    if (e >= N_EDGES) return;
    int s = g_src[e];
    int d = g_dst[e];
    float nr = g_norm[e];
    const float4* ys = reinterpret_cast<const float4*>(g_y + (size_t)s * HID);
    float4* ad = reinterpret_cast<float4*>(g_agg + (size_t)d * HID);
#pragma unroll
    for (int q = 0; q < 4; q++) {
        float4 v = ys[q];
        atomicAdd(&ad[q], make_float4(v.x * nr, v.y * nr, v.z * nr, v.w * nr));
    }
}

// scalar edge scatter for layer 4
__global__ void k_edge_agg1() {
    int e = blockIdx.x * blockDim.x + threadIdx.x;
    if (e >= N_EDGES) return;
    atomicAdd(&g_agg4[g_dst[e]], g_y4[g_src[e]] * g_norm[e]);
}

__global__ void k_zero_out(float* out) { out[0] = 0.f; }

// mean over nodes of relu(agg4 + b4)
__global__ void k_mean(const float* __restrict__ b4, float* __restrict__ out) {
    int i = blockIdx.x * blockDim.x + threadIdx.x;
    float v = 0.f;
    if (i < N_NODES)
        v = fmaxf(g_agg4[i] + b4[0], 0.f) * (1.0f / (float)N_NODES);
#pragma unroll
    for (int o = 16; o > 0; o >>= 1) v += __shfl_down_sync(0xffffffffu, v, o);
    __shared__ float sbuf[8];
    int lane = threadIdx.x & 31, wid = threadIdx.x >> 5;
    if (lane == 0) sbuf[wid] = v;
    __syncthreads();
    if (wid == 0) {
        v = (lane < (int)(blockDim.x >> 5)) ? sbuf[lane] : 0.f;
#pragma unroll
        for (int o = 4; o > 0; o >>= 1) v += __shfl_down_sync(0xffffffffu, v, o);
        if (lane == 0) atomicAdd(out, v);
    }
}

// ---------------- launch ------------------------------------------------------

extern "C" void kernel_launch(void* const* d_in, const int* in_sizes, int n_in,
                              void* d_out, int out_size) {
    const float* vf    = (const float*)d_in[0];
    const void*  edges = d_in[1];
    const float* w     = (const float*)d_in[2];
    const float* W1    = (const float*)d_in[3];
    const float* b1    = (const float*)d_in[4];
    const float* W2    = (const float*)d_in[5];
    const float* b2    = (const float*)d_in[6];
    const float* W3    = (const float*)d_in[7];
    const float* b3    = (const float*)d_in[8];
    const float* W4    = (const float*)d_in[9];
    const float* b4    = (const float*)d_in[10];
    float*       out   = (float*)d_out;

    const int NB_N = (N_NODES + 255) / 256;
    const int NB_E = (N_EDGES + 255) / 256;

    k_detect<<<1, 1>>>((const long long*)edges);
    k_init_deg<<<NB_N, 256>>>();
    k_edge_pre<<<NB_E, 256>>>(edges, w);
    k_dis<<<NB_N, 256>>>();
    k_norm<<<NB_E, 256>>>(w);

    // layer 1
    k_t1<<<NB_N, 256>>>(vf, W1);
    k_edge_agg16<<<NB_E, 256>>>();
    // layer 2
    k_tmid<<<NB_N, 256>>>(W2, b1);
    k_edge_agg16<<<NB_E, 256>>>();
    // layer 3
    k_tmid<<<NB_N, 256>>>(W3, b2);
    k_edge_agg16<<<NB_E, 256>>>();
    // layer 4
    k_t4<<<NB_N, 256>>>(W4, b3);
    k_edge_agg1<<<NB_E, 256>>>();

    k_zero_out<<<1, 1>>>(out);
    k_mean<<<NB_N, 256>>>(b4, out);
}

// round 5
// speedup vs baseline: 1.1234x; 1.1234x over previous
#include <cuda_runtime.h>
#include <cstdint>

#define N_NODES 100000
#define N_EDGES 6400000
#define F_IN    128
#define HID     16

// ---------------- scratch (static device globals; no runtime alloc) ----------
__device__ __align__(16) int    g_src[N_EDGES];
__device__ __align__(16) int    g_dst[N_EDGES];
__device__ __align__(16) float2 g_csr[N_EDGES];       // (src as int bits, norm), dst-grouped
__device__ int   g_cnt[N_NODES];
__device__ int   g_off[N_NODES + 1];
__device__ int   g_cur[N_NODES];
__device__ float g_deg[N_NODES];
__device__ float g_dis[N_NODES];
__device__ __align__(64) float g_y  [N_NODES * HID];  // per-layer messages
__device__ __align__(64) float g_agg[N_NODES * HID];  // per-layer aggregate
__device__ float g_y4[N_NODES];
__device__ int   g_is64;

// ---------------- preprocessing ----------------------------------------------

// Detect whether the edge tensor is int64 or int32 (JAX x64-disabled downcast).
__global__ void k_detect(const long long* __restrict__ e64) {
    int is64 = 1;
#pragma unroll
    for (int i = 0; i < 16; i++) {
        long long v = e64[i];
        if (v < 0 || v >= N_NODES) { is64 = 0; break; }
    }
    g_is64 = is64;
}

__global__ void k_init_nodes() {
    int i = blockIdx.x * blockDim.x + threadIdx.x;
    if (i < N_NODES) { g_deg[i] = 1.0f; g_cnt[i] = 0; }   // self-loop weight 1
}

// edge indices (either dtype) -> int32 scratch + weighted in-degree + count
__global__ void k_edge_pre(const void* __restrict__ edges,
                           const float* __restrict__ w) {
    int e = blockIdx.x * blockDim.x + threadIdx.x;
    if (e >= N_EDGES) return;
    int s, d;
    if (g_is64) {
        const long long* p = (const long long*)edges;
        s = (int)p[e];
        d = (int)p[N_EDGES + e];
    } else {
        const int* p = (const int*)edges;
        s = p[e];
        d = p[N_EDGES + e];
    }
    s = min(max(s, 0), N_NODES - 1);
    d = min(max(d, 0), N_NODES - 1);
    g_src[e] = s;
    g_dst[e] = d;
    atomicAdd(&g_deg[d], w[e]);
    atomicAdd(&g_cnt[d], 1);
}

__global__ void k_dis() {
    int i = blockIdx.x * blockDim.x + threadIdx.x;
    if (i < N_NODES) g_dis[i] = rsqrtf(g_deg[i]);   // deg >= 1 always
}

// single-block exclusive scan of g_cnt -> g_off ; also init g_cur
__global__ void k_scan() {
    __shared__ int warp_sums[32];
    __shared__ int s_carry;
    if (threadIdx.x == 0) s_carry = 0;
    __syncthreads();
    int lane = threadIdx.x & 31, wid = threadIdx.x >> 5;
    for (int base = 0; base < N_NODES; base += 1024) {
        int i = base + (int)threadIdx.x;
        int v = (i < N_NODES) ? g_cnt[i] : 0;
        int x = v;
#pragma unroll
        for (int o = 1; o < 32; o <<= 1) {
            int y = __shfl_up_sync(0xffffffffu, x, o);
            if (lane >= o) x += y;
        }
        if (lane == 31) warp_sums[wid] = x;
        __syncthreads();
        if (wid == 0) {
            int s = warp_sums[lane];
#pragma unroll
            for (int o = 1; o < 32; o <<= 1) {
                int y = __shfl_up_sync(0xffffffffu, s, o);
                if (lane >= o) s += y;
            }
            warp_sums[lane] = s;
        }
        __syncthreads();
        int excl = x - v + (wid > 0 ? warp_sums[wid - 1] : 0) + s_carry;
        if (i < N_NODES) { g_off[i] = excl; g_cur[i] = excl; }
        int block_total = warp_sums[31];
        __syncthreads();
        if (threadIdx.x == 0) s_carry += block_total;
        __syncthreads();
    }
    if (threadIdx.x == 0) g_off[N_NODES] = s_carry;
}

// fill CSR: norm computed inline; nondeterministic order within a node is fine
__global__ void k_csr_fill(const float* __restrict__ w) {
    int e = blockIdx.x * blockDim.x + threadIdx.x;
    if (e >= N_EDGES) return;
    int s = g_src[e];
    int d = g_dst[e];
    float nr = g_dis[s] * w[e] * g_dis[d];
    int pos = atomicAdd(&g_cur[d], 1);
    g_csr[pos] = make_float2(__int_as_float(s), nr);
}

// ---------------- dense transforms --------------------------------------------

// Layer 1: y = x @ W1
__global__ void k_t1(const float* __restrict__ x, const float* __restrict__ W1) {
    __shared__ float Ws[F_IN * HID];
    for (int t = threadIdx.x; t < F_IN * HID; t += blockDim.x) Ws[t] = W1[t];
    __syncthreads();

    int i = blockIdx.x * blockDim.x + threadIdx.x;
    if (i >= N_NODES) return;

    float acc[HID];
#pragma unroll
    for (int c = 0; c < HID; c++) acc[c] = 0.f;

    const float4* xr = reinterpret_cast<const float4*>(x + (size_t)i * F_IN);
#pragma unroll 8
    for (int k4 = 0; k4 < F_IN / 4; k4++) {
        float4 xv = __ldg(&xr[k4]);
        float xk[4] = {xv.x, xv.y, xv.z, xv.w};
#pragma unroll
        for (int j = 0; j < 4; j++) {
            const float4* wrow = reinterpret_cast<const float4*>(&Ws[(k4 * 4 + j) * HID]);
#pragma unroll
            for (int c4 = 0; c4 < 4; c4++) {
                float4 wv = wrow[c4];
                acc[c4*4+0] = fmaf(xk[j], wv.x, acc[c4*4+0]);
                acc[c4*4+1] = fmaf(xk[j], wv.y, acc[c4*4+1]);
                acc[c4*4+2] = fmaf(xk[j], wv.z, acc[c4*4+2]);
                acc[c4*4+3] = fmaf(xk[j], wv.w, acc[c4*4+3]);
            }
        }
    }

    float4* yo = reinterpret_cast<float4*>(g_y + (size_t)i * HID);
#pragma unroll
    for (int q = 0; q < 4; q++)
        yo[q] = make_float4(acc[q*4+0], acc[q*4+1], acc[q*4+2], acc[q*4+3]);
}

// Layers 2/3: a = relu(agg + b_prev); y = a @ W
__global__ void k_tmid(const float* __restrict__ W, const float* __restrict__ bprev) {
    __shared__ float Ws[HID * HID];
    __shared__ float bs[HID];
    for (int t = threadIdx.x; t < HID * HID; t += blockDim.x) Ws[t] = W[t];
    if (threadIdx.x < HID) bs[threadIdx.x] = bprev[threadIdx.x];
    __syncthreads();

    int i = blockIdx.x * blockDim.x + threadIdx.x;
    if (i >= N_NODES) return;

    float a[HID];
    const float4* ar = reinterpret_cast<const float4*>(g_agg + (size_t)i * HID);
#pragma unroll
    for (int q = 0; q < 4; q++) {
        float4 v = ar[q];
        a[q*4+0] = fmaxf(v.x + bs[q*4+0], 0.f);
        a[q*4+1] = fmaxf(v.y + bs[q*4+1], 0.f);
        a[q*4+2] = fmaxf(v.z + bs[q*4+2], 0.f);
        a[q*4+3] = fmaxf(v.w + bs[q*4+3], 0.f);
    }

    float acc[HID];
#pragma unroll
    for (int c = 0; c < HID; c++) acc[c] = 0.f;
#pragma unroll
    for (int k = 0; k < HID; k++) {
        const float4* wrow = reinterpret_cast<const float4*>(&Ws[k * HID]);
#pragma unroll
        for (int c4 = 0; c4 < 4; c4++) {
            float4 wv = wrow[c4];
            acc[c4*4+0] = fmaf(a[k], wv.x, acc[c4*4+0]);
            acc[c4*4+1] = fmaf(a[k], wv.y, acc[c4*4+1]);
            acc[c4*4+2] = fmaf(a[k], wv.z, acc[c4*4+2]);
            acc[c4*4+3] = fmaf(a[k], wv.w, acc[c4*4+3]);
        }
    }

    float4* yo = reinterpret_cast<float4*>(g_y + (size_t)i * HID);
#pragma unroll
    for (int q = 0; q < 4; q++)
        yo[q] = make_float4(acc[q*4+0], acc[q*4+1], acc[q*4+2], acc[q*4+3]);
}

// Layer 4 transform: y4 = relu(agg + b3) @ W4
__global__ void k_t4(const float* __restrict__ W4, const float* __restrict__ b3) {
    __shared__ float W4s[HID];
    __shared__ float bs[HID];
    if (threadIdx.x < HID) { W4s[threadIdx.x] = W4[threadIdx.x]; bs[threadIdx.x] = b3[threadIdx.x]; }
    __syncthreads();

    int i = blockIdx.x * blockDim.x + threadIdx.x;
    if (i >= N_NODES) return;

    const float4* ar = reinterpret_cast<const float4*>(g_agg + (size_t)i * HID);
    float y = 0.f;
#pragma unroll
    for (int q = 0; q < 4; q++) {
        float4 v = ar[q];
        y = fmaf(fmaxf(v.x + bs[q*4+0], 0.f), W4s[q*4+0], y);
        y = fmaf(fmaxf(v.y + bs[q*4+1], 0.f), W4s[q*4+1], y);
        y = fmaf(fmaxf(v.z + bs[q*4+2], 0.f), W4s[q*4+2], y);
        y = fmaf(fmaxf(v.w + bs[q*4+3], 0.f), W4s[q*4+3], y);
    }
    g_y4[i] = y;
}

// ---------------- pull aggregation (no atomics) --------------------------------

// warp per node: agg[i] = sum_{e in CSR[i]} y[src_e]*norm_e + y[i]*dis_i^2
__global__ void k_pull16() {
    int gw = (blockIdx.x * blockDim.x + threadIdx.x) >> 5;
    if (gw >= N_NODES) return;
    int lane = threadIdx.x & 31;
    int beg = g_off[gw], end = g_off[gw + 1];

    float acc[HID];
#pragma unroll
    for (int c = 0; c < HID; c++) acc[c] = 0.f;

    for (int e = beg + lane; e < end; e += 32) {
        float2 sn = __ldg(&g_csr[e]);
        int s = __float_as_int(sn.x);
        float nr = sn.y;
        const float4* ys = reinterpret_cast<const float4*>(g_y + (size_t)s * HID);
#pragma unroll
        for (int q = 0; q < 4; q++) {
            float4 v = __ldg(&ys[q]);
            acc[q*4+0] = fmaf(v.x, nr, acc[q*4+0]);
            acc[q*4+1] = fmaf(v.y, nr, acc[q*4+1]);
            acc[q*4+2] = fmaf(v.z, nr, acc[q*4+2]);
            acc[q*4+3] = fmaf(v.w, nr, acc[q*4+3]);
        }
    }
#pragma unroll
    for (int o = 16; o > 0; o >>= 1)
#pragma unroll
        for (int c = 0; c < HID; c++)
            acc[c] += __shfl_xor_sync(0xffffffffu, acc[c], o);

    if (lane < 4) {
        float dis = g_dis[gw];
        float d2 = dis * dis;
        float4 v = reinterpret_cast<const float4*>(g_y + (size_t)gw * HID)[lane];
        reinterpret_cast<float4*>(g_agg + (size_t)gw * HID)[lane] =
            make_float4(fmaf(v.x, d2, acc[lane*4+0]),
                        fmaf(v.y, d2, acc[lane*4+1]),
                        fmaf(v.z, d2, acc[lane*4+2]),
                        fmaf(v.w, d2, acc[lane*4+3]));
    }
}

// layer-4 pull + fused global mean pool: out += relu(agg4 + b4)/N per node
__global__ void k_pull1(const float* __restrict__ b4, float* __restrict__ out) {
    int gw = (blockIdx.x * blockDim.x + threadIdx.x) >> 5;
    int lane = threadIdx.x & 31;
    int wid = threadIdx.x >> 5;
    __shared__ float sbuf[8];

    float v = 0.f;
    if (gw < N_NODES) {
        int beg = g_off[gw], end = g_off[gw + 1];
        float acc = 0.f;
        for (int e = beg + lane; e < end; e += 32) {
            float2 sn = __ldg(&g_csr[e]);
            acc = fmaf(__ldg(&g_y4[__float_as_int(sn.x)]), sn.y, acc);
        }
#pragma unroll
        for (int o = 16; o > 0; o >>= 1)
            acc += __shfl_xor_sync(0xffffffffu, acc, o);
        float dis = g_dis[gw];
        float agg4 = fmaf(g_y4[gw], dis * dis, acc);
        v = fmaxf(agg4 + b4[0], 0.f) * (1.0f / (float)N_NODES);
    }
    if (lane == 0) sbuf[wid] = v;
    __syncthreads();
    if (wid == 0) {
        v = (lane < (int)(blockDim.x >> 5)) ? sbuf[lane] : 0.f;
#pragma unroll
        for (int o = 4; o > 0; o >>= 1) v += __shfl_down_sync(0xffffffffu, v, o);
        if (lane == 0) atomicAdd(out, v);
    }
}

__global__ void k_zero_out(float* out) { out[0] = 0.f; }

// ---------------- launch ------------------------------------------------------

extern "C" void kernel_launch(void* const* d_in, const int* in_sizes, int n_in,
                              void* d_out, int out_size) {
    const float* vf    = (const float*)d_in[0];
    const void*  edges = d_in[1];
    const float* w     = (const float*)d_in[2];
    const float* W1    = (const float*)d_in[3];
    const float* b1    = (const float*)d_in[4];
    const float* W2    = (const float*)d_in[5];
    const float* b2    = (const float*)d_in[6];
    const float* W3    = (const float*)d_in[7];
    const float* b3    = (const float*)d_in[8];
    const float* W4    = (const float*)d_in[9];
    const float* b4    = (const float*)d_in[10];
    float*       out   = (float*)d_out;

    const int NB_N = (N_NODES + 255) / 256;
    const int NB_E = (N_EDGES + 255) / 256;
    const int NB_W = (N_NODES * 32 + 255) / 256;   // warp-per-node grids

    // ---- CSR build ----
    k_detect<<<1, 1>>>((const long long*)edges);
    k_init_nodes<<<NB_N, 256>>>();
    k_edge_pre<<<NB_E, 256>>>(edges, w);
    k_dis<<<NB_N, 256>>>();
    k_scan<<<1, 1024>>>();
    k_csr_fill<<<NB_E, 256>>>(w);

    // ---- 4 GCN layers (pull aggregation) ----
    k_t1<<<NB_N, 256>>>(vf, W1);
    k_pull16<<<NB_W, 256>>>();
    k_tmid<<<NB_N, 256>>>(W2, b1);
    k_pull16<<<NB_W, 256>>>();
    k_tmid<<<NB_N, 256>>>(W3, b2);
    k_pull16<<<NB_W, 256>>>();
    k_t4<<<NB_N, 256>>>(W4, b3);

    k_zero_out<<<1, 1>>>(out);
    k_pull1<<<NB_W, 256>>>(b4, out);
}

// round 6
// speedup vs baseline: 1.5261x; 1.3584x over previous
#include <cuda_runtime.h>
#include <cstdint>

#define N_NODES 100000
#define N_EDGES 6400000
#define F_IN    128
#define HID     16

// ---------------- scratch (static device globals; no runtime alloc) ----------
__device__ __align__(16) int    g_src[N_EDGES];
__device__ __align__(16) int    g_dst[N_EDGES];
__device__ __align__(16) float2 g_csr[N_EDGES];       // (src as int bits, norm), dst-grouped
__device__ int   g_cnt[N_NODES];
__device__ int   g_off[N_NODES + 1];
__device__ int   g_cur[N_NODES];
__device__ float g_deg[N_NODES];
__device__ float g_dis[N_NODES];
__device__ __align__(64) float g_y  [N_NODES * HID];  // per-layer messages
__device__ __align__(64) float g_agg[N_NODES * HID];  // per-layer aggregate
__device__ float g_y4[N_NODES];
__device__ int   g_is64;

// ---------------- preprocessing ----------------------------------------------

// Detect whether the edge tensor is int64 or int32 (JAX x64-disabled downcast).
__global__ void k_detect(const long long* __restrict__ e64) {
    int is64 = 1;
#pragma unroll
    for (int i = 0; i < 16; i++) {
        long long v = e64[i];
        if (v < 0 || v >= N_NODES) { is64 = 0; break; }
    }
    g_is64 = is64;
}

__global__ void k_init_nodes() {
    int i = blockIdx.x * blockDim.x + threadIdx.x;
    if (i < N_NODES) { g_deg[i] = 1.0f; g_cnt[i] = 0; }   // self-loop weight 1
}

// edge indices (either dtype) -> int32 scratch + weighted in-degree + count
__global__ void k_edge_pre(const void* __restrict__ edges,
                           const float* __restrict__ w) {
    int e = blockIdx.x * blockDim.x + threadIdx.x;
    if (e >= N_EDGES) return;
    int s, d;
    if (g_is64) {
        const long long* p = (const long long*)edges;
        s = (int)p[e];
        d = (int)p[N_EDGES + e];
    } else {
        const int* p = (const int*)edges;
        s = p[e];
        d = p[N_EDGES + e];
    }
    s = min(max(s, 0), N_NODES - 1);
    d = min(max(d, 0), N_NODES - 1);
    g_src[e] = s;
    g_dst[e] = d;
    atomicAdd(&g_deg[d], w[e]);
    atomicAdd(&g_cnt[d], 1);
}

__global__ void k_dis() {
    int i = blockIdx.x * blockDim.x + threadIdx.x;
    if (i < N_NODES) g_dis[i] = rsqrtf(g_deg[i]);   // deg >= 1 always
}

// single-block exclusive scan of g_cnt -> g_off ; also init g_cur
__global__ void k_scan() {
    __shared__ int warp_sums[32];
    __shared__ int s_carry;
    if (threadIdx.x == 0) s_carry = 0;
    __syncthreads();
    int lane = threadIdx.x & 31, wid = threadIdx.x >> 5;
    for (int base = 0; base < N_NODES; base += 1024) {
        int i = base + (int)threadIdx.x;
        int v = (i < N_NODES) ? g_cnt[i] : 0;
        int x = v;
#pragma unroll
        for (int o = 1; o < 32; o <<= 1) {
            int y = __shfl_up_sync(0xffffffffu, x, o);
            if (lane >= o) x += y;
        }
        if (lane == 31) warp_sums[wid] = x;
        __syncthreads();
        if (wid == 0) {
            int s = warp_sums[lane];
#pragma unroll
            for (int o = 1; o < 32; o <<= 1) {
                int y = __shfl_up_sync(0xffffffffu, s, o);
                if (lane >= o) s += y;
            }
            warp_sums[lane] = s;
        }
        __syncthreads();
        int excl = x - v + (wid > 0 ? warp_sums[wid - 1] : 0) + s_carry;
        if (i < N_NODES) { g_off[i] = excl; g_cur[i] = excl; }
        int block_total = warp_sums[31];
        __syncthreads();
        if (threadIdx.x == 0) s_carry += block_total;
        __syncthreads();
    }
    if (threadIdx.x == 0) g_off[N_NODES] = s_carry;
}

// fill CSR: norm computed inline; nondeterministic order within a node is fine
__global__ void k_csr_fill(const float* __restrict__ w) {
    int e = blockIdx.x * blockDim.x + threadIdx.x;
    if (e >= N_EDGES) return;
    int s = g_src[e];
    int d = g_dst[e];
    float nr = g_dis[s] * w[e] * g_dis[d];
    int pos = atomicAdd(&g_cur[d], 1);
    g_csr[pos] = make_float2(__int_as_float(s), nr);
}

// ---------------- dense transforms --------------------------------------------

// Layer 1: y = x @ W1
__global__ void k_t1(const float* __restrict__ x, const float* __restrict__ W1) {
    __shared__ float Ws[F_IN * HID];
    for (int t = threadIdx.x; t < F_IN * HID; t += blockDim.x) Ws[t] = W1[t];
    __syncthreads();

    int i = blockIdx.x * blockDim.x + threadIdx.x;
    if (i >= N_NODES) return;

    float acc[HID];
#pragma unroll
    for (int c = 0; c < HID; c++) acc[c] = 0.f;

    const float4* xr = reinterpret_cast<const float4*>(x + (size_t)i * F_IN);
#pragma unroll 8
    for (int k4 = 0; k4 < F_IN / 4; k4++) {
        float4 xv = __ldg(&xr[k4]);
        float xk[4] = {xv.x, xv.y, xv.z, xv.w};
#pragma unroll
        for (int j = 0; j < 4; j++) {
            const float4* wrow = reinterpret_cast<const float4*>(&Ws[(k4 * 4 + j) * HID]);
#pragma unroll
            for (int c4 = 0; c4 < 4; c4++) {
                float4 wv = wrow[c4];
                acc[c4*4+0] = fmaf(xk[j], wv.x, acc[c4*4+0]);
                acc[c4*4+1] = fmaf(xk[j], wv.y, acc[c4*4+1]);
                acc[c4*4+2] = fmaf(xk[j], wv.z, acc[c4*4+2]);
                acc[c4*4+3] = fmaf(xk[j], wv.w, acc[c4*4+3]);
            }
        }
    }

    float4* yo = reinterpret_cast<float4*>(g_y + (size_t)i * HID);
#pragma unroll
    for (int q = 0; q < 4; q++)
        yo[q] = make_float4(acc[q*4+0], acc[q*4+1], acc[q*4+2], acc[q*4+3]);
}

// Layers 2/3: a = relu(agg + b_prev); y = a @ W
__global__ void k_tmid(const float* __restrict__ W, const float* __restrict__ bprev) {
    __shared__ float Ws[HID * HID];
    __shared__ float bs[HID];
    for (int t = threadIdx.x; t < HID * HID; t += blockDim.x) Ws[t] = W[t];
    if (threadIdx.x < HID) bs[threadIdx.x] = bprev[threadIdx.x];
    __syncthreads();

    int i = blockIdx.x * blockDim.x + threadIdx.x;
    if (i >= N_NODES) return;

    float a[HID];
    const float4* ar = reinterpret_cast<const float4*>(g_agg + (size_t)i * HID);
#pragma unroll
    for (int q = 0; q < 4; q++) {
        float4 v = ar[q];
        a[q*4+0] = fmaxf(v.x + bs[q*4+0], 0.f);
        a[q*4+1] = fmaxf(v.y + bs[q*4+1], 0.f);
        a[q*4+2] = fmaxf(v.z + bs[q*4+2], 0.f);
        a[q*4+3] = fmaxf(v.w + bs[q*4+3], 0.f);
    }

    float acc[HID];
#pragma unroll
    for (int c = 0; c < HID; c++) acc[c] = 0.f;
#pragma unroll
    for (int k = 0; k < HID; k++) {
        const float4* wrow = reinterpret_cast<const float4*>(&Ws[k * HID]);
#pragma unroll
        for (int c4 = 0; c4 < 4; c4++) {
            float4 wv = wrow[c4];
            acc[c4*4+0] = fmaf(a[k], wv.x, acc[c4*4+0]);
            acc[c4*4+1] = fmaf(a[k], wv.y, acc[c4*4+1]);
            acc[c4*4+2] = fmaf(a[k], wv.z, acc[c4*4+2]);
            acc[c4*4+3] = fmaf(a[k], wv.w, acc[c4*4+3]);
        }
    }

    float4* yo = reinterpret_cast<float4*>(g_y + (size_t)i * HID);
#pragma unroll
    for (int q = 0; q < 4; q++)
        yo[q] = make_float4(acc[q*4+0], acc[q*4+1], acc[q*4+2], acc[q*4+3]);
}

// Layer 4 transform: y4 = relu(agg + b3) @ W4
__global__ void k_t4(const float* __restrict__ W4, const float* __restrict__ b3) {
    __shared__ float W4s[HID];
    __shared__ float bs[HID];
    if (threadIdx.x < HID) { W4s[threadIdx.x] = W4[threadIdx.x]; bs[threadIdx.x] = b3[threadIdx.x]; }
    __syncthreads();

    int i = blockIdx.x * blockDim.x + threadIdx.x;
    if (i >= N_NODES) return;

    const float4* ar = reinterpret_cast<const float4*>(g_agg + (size_t)i * HID);
    float y = 0.f;
#pragma unroll
    for (int q = 0; q < 4; q++) {
        float4 v = ar[q];
        y = fmaf(fmaxf(v.x + bs[q*4+0], 0.f), W4s[q*4+0], y);
        y = fmaf(fmaxf(v.y + bs[q*4+1], 0.f), W4s[q*4+1], y);
        y = fmaf(fmaxf(v.z + bs[q*4+2], 0.f), W4s[q*4+2], y);
        y = fmaf(fmaxf(v.w + bs[q*4+3], 0.f), W4s[q*4+3], y);
    }
    g_y4[i] = y;
}

// ---------------- pull aggregation (no atomics) --------------------------------

// warp per node, 4 lanes per edge: minimal L1tex wavefronts on the y[src] gather.
// grp = lane>>2 selects the edge (8 edges per warp-iteration),
// li = lane&3 selects which float4 of the 64B row this lane loads.
__global__ void k_pull16() {
    int gw = (blockIdx.x * blockDim.x + threadIdx.x) >> 5;
    if (gw >= N_NODES) return;
    int lane = threadIdx.x & 31;
    int grp  = lane >> 2;
    int li   = lane & 3;
    int beg = g_off[gw], end = g_off[gw + 1];

    float4 acc = make_float4(0.f, 0.f, 0.f, 0.f);

    int e = beg + grp;
    // 2x unrolled: two independent gathers in flight per lane
    for (; e + 8 < end; e += 16) {
        float2 sn0 = __ldg(&g_csr[e]);
        float2 sn1 = __ldg(&g_csr[e + 8]);
        int   s0 = __float_as_int(sn0.x);
        int   s1 = __float_as_int(sn1.x);
        float4 v0 = __ldg(reinterpret_cast<const float4*>(g_y + (size_t)s0 * HID) + li);
        float4 v1 = __ldg(reinterpret_cast<const float4*>(g_y + (size_t)s1 * HID) + li);
        acc.x = fmaf(v0.x, sn0.y, acc.x);
        acc.y = fmaf(v0.y, sn0.y, acc.y);
        acc.z = fmaf(v0.z, sn0.y, acc.z);
        acc.w = fmaf(v0.w, sn0.y, acc.w);
        acc.x = fmaf(v1.x, sn1.y, acc.x);
        acc.y = fmaf(v1.y, sn1.y, acc.y);
        acc.z = fmaf(v1.z, sn1.y, acc.z);
        acc.w = fmaf(v1.w, sn1.y, acc.w);
    }
    if (e < end) {
        float2 sn = __ldg(&g_csr[e]);
        int s = __float_as_int(sn.x);
        float4 v = __ldg(reinterpret_cast<const float4*>(g_y + (size_t)s * HID) + li);
        acc.x = fmaf(v.x, sn.y, acc.x);
        acc.y = fmaf(v.y, sn.y, acc.y);
        acc.z = fmaf(v.z, sn.y, acc.z);
        acc.w = fmaf(v.w, sn.y, acc.w);
    }

    // reduce across the 8 groups (lane-id masks 4/8/16 preserve li)
#pragma unroll
    for (int m = 4; m <= 16; m <<= 1) {
        acc.x += __shfl_xor_sync(0xffffffffu, acc.x, m);
        acc.y += __shfl_xor_sync(0xffffffffu, acc.y, m);
        acc.z += __shfl_xor_sync(0xffffffffu, acc.z, m);
        acc.w += __shfl_xor_sync(0xffffffffu, acc.w, m);
    }

    if (lane < 4) {
        float dis = g_dis[gw];
        float d2 = dis * dis;
        float4 v = reinterpret_cast<const float4*>(g_y + (size_t)gw * HID)[lane];
        reinterpret_cast<float4*>(g_agg + (size_t)gw * HID)[lane] =
            make_float4(fmaf(v.x, d2, acc.x),
                        fmaf(v.y, d2, acc.y),
                        fmaf(v.z, d2, acc.z),
                        fmaf(v.w, d2, acc.w));
    }
}

// layer-4 pull + fused global mean pool: out += relu(agg4 + b4)/N per node
__global__ void k_pull1(const float* __restrict__ b4, float* __restrict__ out) {
    int gw = (blockIdx.x * blockDim.x + threadIdx.x) >> 5;
    int lane = threadIdx.x & 31;
    int wid = threadIdx.x >> 5;
    __shared__ float sbuf[8];

    float v = 0.f;
    if (gw < N_NODES) {
        int beg = g_off[gw], end = g_off[gw + 1];
        float acc = 0.f;
        for (int e = beg + lane; e < end; e += 32) {
            float2 sn = __ldg(&g_csr[e]);
            acc = fmaf(__ldg(&g_y4[__float_as_int(sn.x)]), sn.y, acc);
        }
#pragma unroll
        for (int o = 16; o > 0; o >>= 1)
            acc += __shfl_xor_sync(0xffffffffu, acc, o);
        float dis = g_dis[gw];
        float agg4 = fmaf(g_y4[gw], dis * dis, acc);
        v = fmaxf(agg4 + b4[0], 0.f) * (1.0f / (float)N_NODES);
    }
    if (lane == 0) sbuf[wid] = v;
    __syncthreads();
    if (wid == 0) {
        v = (lane < (int)(blockDim.x >> 5)) ? sbuf[lane] : 0.f;
#pragma unroll
        for (int o = 4; o > 0; o >>= 1) v += __shfl_down_sync(0xffffffffu, v, o);
        if (lane == 0) atomicAdd(out, v);
    }
}

__global__ void k_zero_out(float* out) { out[0] = 0.f; }

// ---------------- launch ------------------------------------------------------

extern "C" void kernel_launch(void* const* d_in, const int* in_sizes, int n_in,
                              void* d_out, int out_size) {
    const float* vf    = (const float*)d_in[0];
    const void*  edges = d_in[1];
    const float* w     = (const float*)d_in[2];
    const float* W1    = (const float*)d_in[3];
    const float* b1    = (const float*)d_in[4];
    const float* W2    = (const float*)d_in[5];
    const float* b2    = (const float*)d_in[6];
    const float* W3    = (const float*)d_in[7];
    const float* b3    = (const float*)d_in[8];
    const float* W4    = (const float*)d_in[9];
    const float* b4    = (const float*)d_in[10];
    float*       out   = (float*)d_out;

    const int NB_N = (N_NODES + 255) / 256;
    const int NB_E = (N_EDGES + 255) / 256;
    const int NB_W = (N_NODES * 32 + 255) / 256;   // warp-per-node grids

    // ---- CSR build ----
    k_detect<<<1, 1>>>((const long long*)edges);
    k_init_nodes<<<NB_N, 256>>>();
    k_edge_pre<<<NB_E, 256>>>(edges, w);
    k_dis<<<NB_N, 256>>>();
    k_scan<<<1, 1024>>>();
    k_csr_fill<<<NB_E, 256>>>(w);

    // ---- 4 GCN layers (pull aggregation) ----
    k_t1<<<NB_N, 256>>>(vf, W1);
    k_pull16<<<NB_W, 256>>>();
    k_tmid<<<NB_N, 256>>>(W2, b1);
    k_pull16<<<NB_W, 256>>>();
    k_tmid<<<NB_N, 256>>>(W3, b2);
    k_pull16<<<NB_W, 256>>>();
    k_t4<<<NB_N, 256>>>(W4, b3);

    k_zero_out<<<1, 1>>>(out);
    k_pull1<<<NB_W, 256>>>(b4, out);
}

// round 8
// speedup vs baseline: 2.0598x; 1.3497x over previous
#include <cuda_runtime.h>
#include <cuda_fp16.h>
#include <cstdint>

#define N_NODES 100000
#define N_EDGES 6400000
#define F_IN    128
#define HID     16
#define SCAN_BLK 1024
#define NB_SCAN ((N_NODES + SCAN_BLK - 1) / SCAN_BLK)   // 98

// ---------------- scratch (static device globals; no runtime alloc) ----------
__device__ __align__(16) int    g_src[N_EDGES];
__device__ __align__(16) int    g_dst[N_EDGES];
__device__ __align__(16) float2 g_csr[N_EDGES];        // (src as int bits, w), dst-grouped
__device__ unsigned long long   g_degcnt[N_NODES];      // [cnt:22][deg fixed 2^-22:42]
__device__ int   g_off[N_NODES + 1];
__device__ int   g_cur[N_NODES];
__device__ float g_dis[N_NODES];
__device__ int   g_bsum[NB_SCAN];
__device__ __align__(32) __half g_yh [N_NODES * HID];  // prescaled messages y*dis (fp16)
__device__ __align__(64) float  g_agg[N_NODES * HID];  // true aggregate (fp32)
__device__ float g_y4h[N_NODES];                        // layer-4 prescaled message
__device__ int   g_is64;

// ---------------- preprocessing ----------------------------------------------

__global__ void k_detect(const long long* __restrict__ e64) {
    int is64 = 1;
#pragma unroll
    for (int i = 0; i < 16; i++) {
        long long v = e64[i];
        if (v < 0 || v >= N_NODES) { is64 = 0; break; }
    }
    g_is64 = is64;
}

__global__ void k_init_nodes() {
    int i = blockIdx.x * blockDim.x + threadIdx.x;
    if (i < N_NODES) g_degcnt[i] = (1ull << 22);   // deg = 1.0 (self-loop), cnt = 0
}

// edge indices (either dtype) -> int32 scratch + ONE packed atomic (cnt + deg)
__global__ void k_edge_pre(const void* __restrict__ edges,
                           const float* __restrict__ w) {
    int e = blockIdx.x * blockDim.x + threadIdx.x;
    if (e >= N_EDGES) return;
    int s, d;
    if (g_is64) {
        const long long* p = (const long long*)edges;
        s = (int)p[e];
        d = (int)p[N_EDGES + e];
    } else {
        const int* p = (const int*)edges;
        s = p[e];
        d = p[N_EDGES + e];
    }
    s = min(max(s, 0), N_NODES - 1);
    d = min(max(d, 0), N_NODES - 1);
    g_src[e] = s;
    g_dst[e] = d;
    unsigned long long pack =
        (1ull << 42) | (unsigned long long)(w[e] * 4194304.0f);  // w * 2^22
    atomicAdd(&g_degcnt[d], pack);
}

// scan phase 1: per-block exclusive scan of counts; also compute dis
__global__ void k_scan1() {
    __shared__ int ws[32];
    int b = blockIdx.x, t = threadIdx.x;
    int i = b * SCAN_BLK + t;
    int lane = t & 31, wid = t >> 5;

    int v = 0;
    if (i < N_NODES) {
        unsigned long long dc = g_degcnt[i];
        v = (int)(dc >> 42);
        float deg = (float)(dc & ((1ull << 42) - 1)) * (1.0f / 4194304.0f);
        g_dis[i] = rsqrtf(deg);
    }
    int x = v;
#pragma unroll
    for (int o = 1; o < 32; o <<= 1) {
        int y = __shfl_up_sync(0xffffffffu, x, o);
        if (lane >= o) x += y;
    }
    if (lane == 31) ws[wid] = x;
    __syncthreads();
    if (wid == 0) {
        int s = ws[lane];
#pragma unroll
        for (int o = 1; o < 32; o <<= 1) {
            int y = __shfl_up_sync(0xffffffffu, s, o);
            if (lane >= o) s += y;
        }
        ws[lane] = s;
    }
    __syncthreads();
    int excl = x - v + (wid > 0 ? ws[wid - 1] : 0);
    if (i < N_NODES) g_off[i] = excl;
    if (t == SCAN_BLK - 1) g_bsum[b] = excl + v;
}

// scan phase 2: exclusive scan of NB_SCAN block totals (single block, 128 thr)
__global__ void k_scan2() {
    __shared__ int ws[4];
    int t = threadIdx.x;
    int lane = t & 31, wid = t >> 5;
    int v = (t < NB_SCAN) ? g_bsum[t] : 0;
    int x = v;
#pragma unroll
    for (int o = 1; o < 32; o <<= 1) {
        int y = __shfl_up_sync(0xffffffffu, x, o);
        if (lane >= o) x += y;
    }
    if (lane == 31) ws[wid] = x;
    __syncthreads();
    if (wid == 0 && lane < 4) {
        int s = ws[lane];
#pragma unroll
        for (int o = 1; o < 4; o <<= 1) {
            int y = __shfl_up_sync(0x0000000fu, s, o);
            if (lane >= o) s += y;
        }
        ws[lane] = s;
    }
    __syncthreads();
    int excl = x - v + (wid > 0 ? ws[wid - 1] : 0);
    if (t < NB_SCAN) g_bsum[t] = excl;
}

// scan phase 3: add block offsets; init cursors; finalize sentinel
__global__ void k_scan3() {
    int i = blockIdx.x * blockDim.x + threadIdx.x;
    if (i < N_NODES) {
        int o = g_off[i] + g_bsum[i / SCAN_BLK];
        g_off[i] = o;
        g_cur[i] = o;
    }
    if (i == 0) g_off[N_NODES] = N_EDGES;
}

// fill CSR: pure placement, no dis gathers (norm applied at pull time)
__global__ void k_csr_fill(const float* __restrict__ w) {
    int e = blockIdx.x * blockDim.x + threadIdx.x;
    if (e >= N_EDGES) return;
    int s = g_src[e];
    int d = g_dst[e];
    int pos = atomicAdd(&g_cur[d], 1);
    g_csr[pos] = make_float2(__int_as_float(s), w[e]);
}

// ---------------- dense transforms (write prescaled fp16 messages) -----------

__device__ __forceinline__ void store_yh(int i, const float* acc, float dis) {
    __half2 hp[8];
#pragma unroll
    for (int c = 0; c < 8; c++)
        hp[c] = __floats2half2_rn(acc[2*c] * dis, acc[2*c+1] * dis);
    uint4* yo = reinterpret_cast<uint4*>(g_yh + (size_t)i * HID);
    yo[0] = *reinterpret_cast<uint4*>(&hp[0]);
    yo[1] = *reinterpret_cast<uint4*>(&hp[4]);
}

// Layer 1: y = x @ W1 ; store yh = y*dis
__global__ void k_t1(const float* __restrict__ x, const float* __restrict__ W1) {
    __shared__ float Ws[F_IN * HID];
    for (int t = threadIdx.x; t < F_IN * HID; t += blockDim.x) Ws[t] = W1[t];
    __syncthreads();

    int i = blockIdx.x * blockDim.x + threadIdx.x;
    if (i >= N_NODES) return;

    float acc[HID];
#pragma unroll
    for (int c = 0; c < HID; c++) acc[c] = 0.f;

    const float4* xr = reinterpret_cast<const float4*>(x + (size_t)i * F_IN);
#pragma unroll 8
    for (int k4 = 0; k4 < F_IN / 4; k4++) {
        float4 xv = __ldg(&xr[k4]);
        float xk[4] = {xv.x, xv.y, xv.z, xv.w};
#pragma unroll
        for (int j = 0; j < 4; j++) {
            const float4* wrow = reinterpret_cast<const float4*>(&Ws[(k4 * 4 + j) * HID]);
#pragma unroll
            for (int c4 = 0; c4 < 4; c4++) {
                float4 wv = wrow[c4];
                acc[c4*4+0] = fmaf(xk[j], wv.x, acc[c4*4+0]);
                acc[c4*4+1] = fmaf(xk[j], wv.y, acc[c4*4+1]);
                acc[c4*4+2] = fmaf(xk[j], wv.z, acc[c4*4+2]);
                acc[c4*4+3] = fmaf(xk[j], wv.w, acc[c4*4+3]);
            }
        }
    }
    store_yh(i, acc, g_dis[i]);
}

// Layers 2/3: a = relu(agg + b_prev); y = a @ W ; store yh = y*dis
__global__ void k_tmid(const float* __restrict__ W, const float* __restrict__ bprev) {
    __shared__ float Ws[HID * HID];
    __shared__ float bs[HID];
    for (int t = threadIdx.x; t < HID * HID; t += blockDim.x) Ws[t] = W[t];
    if (threadIdx.x < HID) bs[threadIdx.x] = bprev[threadIdx.x];
    __syncthreads();

    int i = blockIdx.x * blockDim.x + threadIdx.x;
    if (i >= N_NODES) return;

    float a[HID];
    const float4* ar = reinterpret_cast<const float4*>(g_agg + (size_t)i * HID);
#pragma unroll
    for (int q = 0; q < 4; q++) {
        float4 v = ar[q];
        a[q*4+0] = fmaxf(v.x + bs[q*4+0], 0.f);
        a[q*4+1] = fmaxf(v.y + bs[q*4+1], 0.f);
        a[q*4+2] = fmaxf(v.z + bs[q*4+2], 0.f);
        a[q*4+3] = fmaxf(v.w + bs[q*4+3], 0.f);
    }

    float acc[HID];
#pragma unroll
    for (int c = 0; c < HID; c++) acc[c] = 0.f;
#pragma unroll
    for (int k = 0; k < HID; k++) {
        const float4* wrow = reinterpret_cast<const float4*>(&Ws[k * HID]);
#pragma unroll
        for (int c4 = 0; c4 < 4; c4++) {
            float4 wv = wrow[c4];
            acc[c4*4+0] = fmaf(a[k], wv.x, acc[c4*4+0]);
            acc[c4*4+1] = fmaf(a[k], wv.y, acc[c4*4+1]);
            acc[c4*4+2] = fmaf(a[k], wv.z, acc[c4*4+2]);
            acc[c4*4+3] = fmaf(a[k], wv.w, acc[c4*4+3]);
        }
    }
    store_yh(i, acc, g_dis[i]);
}

// Layer 4: y4 = relu(agg + b3) @ W4 ; store y4h = y4*dis
__global__ void k_t4(const float* __restrict__ W4, const float* __restrict__ b3) {
    __shared__ float W4s[HID];
    __shared__ float bs[HID];
    if (threadIdx.x < HID) { W4s[threadIdx.x] = W4[threadIdx.x]; bs[threadIdx.x] = b3[threadIdx.x]; }
    __syncthreads();

    int i = blockIdx.x * blockDim.x + threadIdx.x;
    if (i >= N_NODES) return;

    const float4* ar = reinterpret_cast<const float4*>(g_agg + (size_t)i * HID);
    float y = 0.f;
#pragma unroll
    for (int q = 0; q < 4; q++) {
        float4 v = ar[q];
        y = fmaf(fmaxf(v.x + bs[q*4+0], 0.f), W4s[q*4+0], y);
        y = fmaf(fmaxf(v.y + bs[q*4+1], 0.f), W4s[q*4+1], y);
        y = fmaf(fmaxf(v.z + bs[q*4+2], 0.f), W4s[q*4+2], y);
        y = fmaf(fmaxf(v.w + bs[q*4+3], 0.f), W4s[q*4+3], y);
    }
    g_y4h[i] = y * g_dis[i];
}

// ---------------- pull aggregation (no atomics) --------------------------------

__device__ __forceinline__ void acc8(uint4 v, float wgt, float* acc) {
    float2 f;
    f = __half22float2(*reinterpret_cast<__half2*>(&v.x));
    acc[0] = fmaf(f.x, wgt, acc[0]); acc[1] = fmaf(f.y, wgt, acc[1]);
    f = __half22float2(*reinterpret_cast<__half2*>(&v.y));
    acc[2] = fmaf(f.x, wgt, acc[2]); acc[3] = fmaf(f.y, wgt, acc[3]);
    f = __half22float2(*reinterpret_cast<__half2*>(&v.z));
    acc[4] = fmaf(f.x, wgt, acc[4]); acc[5] = fmaf(f.y, wgt, acc[5]);
    f = __half22float2(*reinterpret_cast<__half2*>(&v.w));
    acc[6] = fmaf(f.x, wgt, acc[6]); acc[7] = fmaf(f.y, wgt, acc[7]);
}

// warp per node, 2 lanes per edge (16 edges / warp-iter), fp16 rows:
// agg[d] = dis[d] * ( sum_e w_e * yh[src_e]  +  yh[d] )
__global__ void k_pull16() {
    int gw = (blockIdx.x * blockDim.x + threadIdx.x) >> 5;
    if (gw >= N_NODES) return;
    int lane = threadIdx.x & 31;
    int grp  = lane >> 1;          // edge slot 0..15
    int li   = lane & 1;           // which 16B half of the 32B row
    int beg = g_off[gw], end = g_off[gw + 1];

    float acc[8];
#pragma unroll
    for (int c = 0; c < 8; c++) acc[c] = 0.f;

    int e = beg + grp;
    for (; e + 16 < end; e += 32) {
        float2 sn0 = __ldg(&g_csr[e]);
        float2 sn1 = __ldg(&g_csr[e + 16]);
        int s0 = __float_as_int(sn0.x);
        int s1 = __float_as_int(sn1.x);
        uint4 v0 = __ldg(reinterpret_cast<const uint4*>(g_yh + (size_t)s0 * HID) + li);
        uint4 v1 = __ldg(reinterpret_cast<const uint4*>(g_yh + (size_t)s1 * HID) + li);
        acc8(v0, sn0.y, acc);
        acc8(v1, sn1.y, acc);
    }
    if (e < end) {
        float2 sn = __ldg(&g_csr[e]);
        int s = __float_as_int(sn.x);
        uint4 v = __ldg(reinterpret_cast<const uint4*>(g_yh + (size_t)s * HID) + li);
        acc8(v, sn.y, acc);
    }

    // reduce across the 16 edge slots (masks 2..16 preserve li)
#pragma unroll
    for (int m = 2; m <= 16; m <<= 1)
#pragma unroll
        for (int c = 0; c < 8; c++)
            acc[c] += __shfl_xor_sync(0xffffffffu, acc[c], m);

    if (lane < 2) {
        // self-loop term + final dis[d] scaling
        uint4 v = __ldg(reinterpret_cast<const uint4*>(g_yh + (size_t)gw * HID) + li);
        acc8(v, 1.0f, acc);
        float dis = g_dis[gw];
        float4* ao = reinterpret_cast<float4*>(g_agg + (size_t)gw * HID);
        ao[li*2]     = make_float4(acc[0]*dis, acc[1]*dis, acc[2]*dis, acc[3]*dis);
        ao[li*2 + 1] = make_float4(acc[4]*dis, acc[5]*dis, acc[6]*dis, acc[7]*dis);
    }
}

// layer-4 pull + fused global mean pool
__global__ void k_pull1(const float* __restrict__ b4, float* __restrict__ out) {
    int gw = (blockIdx.x * blockDim.x + threadIdx.x) >> 5;
    int lane = threadIdx.x & 31;
    int wid = threadIdx.x >> 5;
    __shared__ float sbuf[8];

    float v = 0.f;
    if (gw < N_NODES) {
        int beg = g_off[gw], end = g_off[gw + 1];
        float acc = 0.f;
        for (int e = beg + lane; e < end; e += 32) {
            float2 sn = __ldg(&g_csr[e]);
            acc = fmaf(__ldg(&g_y4h[__float_as_int(sn.x)]), sn.y, acc);
        }
#pragma unroll
        for (int o = 16; o > 0; o >>= 1)
            acc += __shfl_xor_sync(0xffffffffu, acc, o);
        float agg4 = (acc + g_y4h[gw]) * g_dis[gw];
        v = fmaxf(agg4 + b4[0], 0.f) * (1.0f / (float)N_NODES);
    }
    if (lane == 0) sbuf[wid] = v;
    __syncthreads();
    if (wid == 0) {
        v = (lane < (int)(blockDim.x >> 5)) ? sbuf[lane] : 0.f;
#pragma unroll
        for (int o = 4; o > 0; o >>= 1) v += __shfl_down_sync(0xffffffffu, v, o);
        if (lane == 0) atomicAdd(out, v);
    }
}

__global__ void k_zero_out(float* out) { out[0] = 0.f; }

// ---------------- launch ------------------------------------------------------

extern "C" void kernel_launch(void* const* d_in, const int* in_sizes, int n_in,
                              void* d_out, int out_size) {
    const float* vf    = (const float*)d_in[0];
    const void*  edges = d_in[1];
    const float* w     = (const float*)d_in[2];
    const float* W1    = (const float*)d_in[3];
    const float* b1    = (const float*)d_in[4];
    const float* W2    = (const float*)d_in[5];
    const float* b2    = (const float*)d_in[6];
    const float* W3    = (const float*)d_in[7];
    const float* b3    = (const float*)d_in[8];
    const float* W4    = (const float*)d_in[9];
    const float* b4    = (const float*)d_in[10];
    float*       out   = (float*)d_out;

    const int NB_N = (N_NODES + 255) / 256;
    const int NB_E = (N_EDGES + 255) / 256;
    const int NB_W = (N_NODES * 32 + 255) / 256;   // warp-per-node grids

    // ---- CSR build ----
    k_detect<<<1, 1>>>((const long long*)edges);
    k_init_nodes<<<NB_N, 256>>>();
    k_edge_pre<<<NB_E, 256>>>(edges, w);
    k_scan1<<<NB_SCAN, SCAN_BLK>>>();
    k_scan2<<<1, 128>>>();
    k_scan3<<<NB_N, 256>>>();
    k_csr_fill<<<NB_E, 256>>>(w);

    // ---- 4 GCN layers (pull aggregation) ----
    k_t1<<<NB_N, 256>>>(vf, W1);
    k_pull16<<<NB_W, 256>>>();
    k_tmid<<<NB_N, 256>>>(W2, b1);
    k_pull16<<<NB_W, 256>>>();
    k_tmid<<<NB_N, 256>>>(W3, b2);
    k_pull16<<<NB_W, 256>>>();
    k_t4<<<NB_N, 256>>>(W4, b3);

    k_zero_out<<<1, 1>>>(out);
    k_pull1<<<NB_W, 256>>>(b4, out);
}